// round 16
// baseline (speedup 1.0000x reference)
#include <cuda_runtime.h>
#include <cuda_fp16.h>
#include <cstdint>
#include <cstddef>

// Problem constants
#define B_   16
#define CIN  512
#define HW   4096
#define G_   8
#define EPSG 1e-5f
#define STILES 32           // HW / 128

// GEMM: CTA tile M=128, N=128, K=512, k-stage 32, 4-deep cp.async ring, 2 CTA/SM
#define AS_LD 20            // A k-row stride in words (16 data + 4 pad)
#define BS_LD 68            // B k-row stride in words (64 data + 4 pad)
#define A_STG 10240         // 128 rows * 80 B
#define B_STG 8704          // 32 k-rows * 272 B
#define STG   18944
#define SMEM_GEMM (4*STG)   // 75776 -> 2 CTAs/SM
#define DMP_LD 130          // att g-dump row stride (floats), even

// merged prep grid
#define NPX 32768           // prepX CTAs (256 float4 each)
#define NPA 1024            // prepA CTAs (one g_AW row each)

// ---------------- device scratch ----------------
// rows 0..511: Wcomb ; rows 512..1023: 4 chunks of [Wp(64);Wg(64)]
__device__ __half g_AW[1024*CIN];
__device__ __half g_x16[(size_t)B_*CIN*HW];      // x fp16 (67 MB)
__device__ __half g_u[(size_t)B_*CIN*HW];        // u fp16 (67 MB)
__device__ float  g_attp[B_*G_*STILES];
__device__ float  g_sump[B_*G_*STILES];
__device__ float  g_sumsqp[B_*G_*STILES];

// ---------------- PTX helpers ----------------
__device__ __forceinline__ uint32_t smem_u32(const void* p) {
    uint32_t a;
    asm("{ .reg .u64 t; cvta.to.shared.u64 t, %1; cvt.u32.u64 %0, t; }" : "=r"(a) : "l"(p));
    return a;
}
__device__ __forceinline__ void cpasync16(uint32_t dst, const void* src) {
    asm volatile("cp.async.cg.shared.global [%0], [%1], 16;" :: "r"(dst), "l"(src) : "memory");
}
#define CP_COMMIT()  asm volatile("cp.async.commit_group;" ::: "memory")
#define CP_WAIT(n)   asm volatile("cp.async.wait_group %0;" :: "n"(n) : "memory")

__device__ __forceinline__ void ldsm4(unsigned* r, uint32_t a) {
    asm volatile("ldmatrix.sync.aligned.m8n8.x4.shared.b16 {%0,%1,%2,%3}, [%4];"
        : "=r"(r[0]), "=r"(r[1]), "=r"(r[2]), "=r"(r[3]) : "r"(a));
}
__device__ __forceinline__ void ldsm4t(unsigned* r, uint32_t a) {
    asm volatile("ldmatrix.sync.aligned.m8n8.x4.trans.shared.b16 {%0,%1,%2,%3}, [%4];"
        : "=r"(r[0]), "=r"(r[1]), "=r"(r[2]), "=r"(r[3]) : "r"(a));
}
__device__ __forceinline__ void mma16(float* c, const unsigned* a, const unsigned* b) {
    asm volatile(
        "mma.sync.aligned.m16n8k16.row.col.f32.f16.f16.f32 "
        "{%0,%1,%2,%3}, {%4,%5,%6,%7}, {%8,%9}, {%0,%1,%2,%3};\n"
        : "+f"(c[0]), "+f"(c[1]), "+f"(c[2]), "+f"(c[3])
        : "r"(a[0]), "r"(a[1]), "r"(a[2]), "r"(a[3]), "r"(b[0]), "r"(b[1]));
}
__device__ __forceinline__ float wred(float v) {
#pragma unroll
    for (int o = 16; o; o >>= 1) v += __shfl_down_sync(0xffffffffu, v, o);
    return v;
}

// ---------------- K1: merged prep (prepX | prepA), one launch ----------------
__global__ void k_prep(const float* __restrict__ x,  const float* __restrict__ Wt,
                       const float* __restrict__ Wz, const float* __restrict__ Wp,
                       const float* __restrict__ Wg) {
    const int cta = blockIdx.x;
    const int tid = threadIdx.x;

    if (cta < NPX) {
        // ----- prepX: 256 float4 -> fp16 (x is read-once here; gemm reads the fp16 copy) -----
        size_t i = (size_t)cta * 256 + tid;
        float4 v = __ldcs(&((const float4*)x)[i]);
        __half2* d = (__half2*)g_x16;
        d[2*i]     = __floats2half2_rn(v.x, v.y);
        d[2*i + 1] = __floats2half2_rn(v.z, v.w);
    } else {
        // ----- prepA: one g_AW row -----
        const int r = cta - NPX;          // 0..1023
        __half* dst = g_AW + (size_t)r*CIN;
        if (r < 512) {
            int g = r >> 6, o = r & 63;
            __shared__ float wz[32];
            if (tid < 32) wz[tid] = Wz[(size_t)(g*64 + o)*32 + tid];
            __syncthreads();
#pragma unroll
            for (int q = 0; q < 2; q++) {
                int i = tid + q*256;
                float a = 0.f;
#pragma unroll 8
                for (int c = 0; c < 32; c++)
                    a += wz[c] * Wt[(size_t)(g*32 + c)*CIN + i];
                dst[i] = __float2half(a);
            }
        } else {
            int idx = r - 512;
            int chunk = idx >> 7, row = idx & 127;
            const float* src = (row < 64) ? Wp + (size_t)(chunk*64 + row)*CIN
                                          : Wg + (size_t)(chunk*64 + row - 64)*CIN;
#pragma unroll
            for (int q = 0; q < 2; q++) {
                int i = tid + q*256;
                dst[i] = __float2half(src[i]);
            }
        }
    }
}

// ---------------- K2: unified GEMM (round-7/15 proven) ----------------
// yy<4: C = Wcomb[yy*128..] @ X  -> u + GN partials
// yy>=4: C = [Wp;Wg](chunk yy-4) @ X -> att partials
__global__ void __launch_bounds__(256, 2)
k_gemm() {
    extern __shared__ char smem[];
    const uint32_t sb = smem_u32(smem);
    __shared__ float rbuf[16];

    const int tid  = threadIdx.x;
    const int lane = tid & 31, warp = tid >> 5;
    const int wm = warp >> 1, wn = warp & 1;     // 4m x 2n warps; warp tile 32m x 64n
    const int stile = blockIdx.x, yy = blockIdx.y, b = blockIdx.z;
    const int scol0 = stile * 128;

    // cp.async loaders
    const int arow = tid >> 1, ah = tid & 1;     // A: 2 chunks/thread
    const __half* asrc = g_AW + ((size_t)yy*128 + arow)*CIN + ah*16;
    const uint32_t adst = sb + arow*80 + ah*32;
    const int bk = (tid >> 4), bn16 = tid & 15;  // B: 2 chunks/thread
    const __half* bsrc0 = g_x16 + ((size_t)b*CIN + bk)*HW + scol0 + bn16*8;
    const uint32_t bdst = sb + A_STG + bk*272 + bn16*16;

    auto issue = [&](int s) {
        if (s < 16) {
            const int st = (s & 3)*STG;
            cpasync16(adst + st,      asrc + s*32);
            cpasync16(adst + st + 16, asrc + s*32 + 8);
            cpasync16(bdst + st,            bsrc0 + (size_t)s*32*HW);
            cpasync16(bdst + st + 16*272,   bsrc0 + (size_t)(s*32 + 16)*HW);
        }
        CP_COMMIT();
    };

    const int a_row = wm*32 + (lane & 15);
    const int a_kw  = (lane >> 4) * 4;
    const int b_k   = lane & 15;
    const int b_w   = (lane >> 4) * 4;

    float acc[2][8][4];
#pragma unroll
    for (int mt = 0; mt < 2; mt++)
#pragma unroll
        for (int nt = 0; nt < 8; nt++)
#pragma unroll
            for (int i = 0; i < 4; i++) acc[mt][nt][i] = 0.f;

    issue(0);
    issue(1);

    for (int s = 0; s < 16; s++) {
        issue(s + 2);
        CP_WAIT(2);
        __syncthreads();
        const uint32_t abuf = sb + (s & 3)*STG;
        const uint32_t bbuf = abuf + A_STG;
#pragma unroll
        for (int ks = 0; ks < 2; ks++) {
            unsigned af[2][4], bf[4][4];
#pragma unroll
            for (int mt = 0; mt < 2; mt++)
                ldsm4(af[mt], abuf + ((a_row + mt*16)*AS_LD + ks*8 + a_kw)*4);
#pragma unroll
            for (int ng = 0; ng < 4; ng++)
                ldsm4t(bf[ng], bbuf + ((ks*16 + b_k)*BS_LD + wn*32 + ng*8 + b_w)*4);
#pragma unroll
            for (int mt = 0; mt < 2; mt++)
#pragma unroll
                for (int ng = 0; ng < 4; ng++) {
                    mma16(acc[mt][2*ng],     af[mt], &bf[ng][0]);
                    mma16(acc[mt][2*ng + 1], af[mt], &bf[ng][2]);
                }
        }
    }
    CP_WAIT(0);
    __syncthreads();

    const int lr = lane >> 2, lc2 = (lane & 3)*2;

    if (yy < 4) {
        // ---- u epilogue: channels yy*128 + wm*32 + ... ----
        float s1 = 0.f, s2 = 0.f;
        const size_t ub = ((size_t)b*CIN + yy*128 + wm*32)*HW + scol0 + wn*64;
#pragma unroll
        for (int mt = 0; mt < 2; mt++)
#pragma unroll
            for (int nt = 0; nt < 8; nt++)
#pragma unroll
                for (int i2 = 0; i2 < 2; i2++) {
                    float v0 = acc[mt][nt][i2*2], v1 = acc[mt][nt][i2*2 + 1];
                    int r = mt*16 + lr + i2*8;
                    int c = nt*8 + lc2;
                    *(__half2*)&g_u[ub + (size_t)r*HW + c] = __floats2half2_rn(v0, v1);
                    s1 += v0 + v1;
                    s2 += v0*v0 + v1*v1;
                }
        s1 = wred(s1); s2 = wred(s2);
        if (lane == 0) { rbuf[warp] = s1; rbuf[8 + warp] = s2; }
        __syncthreads();
        if (tid < 2) {
            int g = yy*2 + tid;
            float ss = rbuf[tid*4] + rbuf[tid*4+1] + rbuf[tid*4+2] + rbuf[tid*4+3];
            float qq = rbuf[8+tid*4] + rbuf[8+tid*4+1] + rbuf[8+tid*4+2] + rbuf[8+tid*4+3];
            g_sump[(b*G_ + g)*STILES + stile]   = ss;
            g_sumsqp[(b*G_ + g)*STILES + stile] = qq;
        }
    } else {
        // ---- att epilogue: rows 0-63 = p, 64-127 = g ; pair warp wm <-> wm+2 ----
        const int yc = yy - 4;
        float* dmp = (float*)smem;   // [64][DMP_LD]
        if (wm >= 2) {
#pragma unroll
            for (int mt = 0; mt < 2; mt++)
#pragma unroll
                for (int nt = 0; nt < 8; nt++)
#pragma unroll
                    for (int i2 = 0; i2 < 2; i2++) {
                        int r = (wm - 2)*32 + mt*16 + lr + i2*8;
                        int c = wn*64 + nt*8 + lc2;
                        *(float2*)&dmp[r*DMP_LD + c] =
                            make_float2(acc[mt][nt][i2*2], acc[mt][nt][i2*2+1]);
                    }
        }
        __syncthreads();
        if (wm < 2) {
            float pg = 0.f;
#pragma unroll
            for (int mt = 0; mt < 2; mt++)
#pragma unroll
                for (int nt = 0; nt < 8; nt++)
#pragma unroll
                    for (int i2 = 0; i2 < 2; i2++) {
                        int r = wm*32 + mt*16 + lr + i2*8;
                        int c = wn*64 + nt*8 + lc2;
                        pg += acc[mt][nt][i2*2]     * dmp[r*DMP_LD + c]
                            + acc[mt][nt][i2*2 + 1] * dmp[r*DMP_LD + c + 1];
                    }
            pg = wred(pg);
            if (lane == 0) rbuf[warp] = pg;
        }
        __syncthreads();
        if (tid < 2) {
            float a = rbuf[tid*2] + rbuf[tid*2 + 1];
            g_attp[(b*G_ + yc*2 + tid)*STILES + stile] = a;
        }
    }
}

// ---------------- K3: fused stats + out = scale*u + bias + x ----------------
// Each CTA covers 1024 contiguous elements = quarter of one (b,c) row -> one GN group.
__global__ void k_final(const float* __restrict__ gamma, const float* __restrict__ beta,
                        float* __restrict__ out) {
    const int cta = blockIdx.x, tid = threadIdx.x;
    const size_t e0 = (size_t)cta << 10;          // first element
    const int b = (int)(e0 >> 21);                // 512*4096 = 2^21
    const int c = (int)((e0 >> 12) & 511);        // HW = 2^12
    const int g = c >> 6;

    __shared__ float s_sc, s_bi;
    if (tid < 32) {
        const int base = (b*G_ + g)*STILES + tid;
        float sm = g_sump[base];
        float sq = g_sumsqp[base];
        float at = g_attp[base];
        sm = wred(sm); sq = wred(sq); at = wred(at);
        if (tid == 0) {
            const float n = 64.0f * 4096.0f;
            float mu  = sm / n;
            float var = fmaxf(sq / n - mu*mu, 0.f);
            float rstd = rsqrtf(at*at*var + EPSG);   // var_z = att^2 * var_u
            float S = at * rstd;
            float gm = gamma[c];
            s_sc = S * gm;
            s_bi = beta[c] - S * mu * gm;
        }
    }
    __syncthreads();
    const float sc = s_sc, bi = s_bi;

    const size_t i = (size_t)cta * 256 + tid;      // float4 index
    const __half2* up = (const __half2*)g_u;
    const __half2* xp = (const __half2*)g_x16;
    __half2 uh0 = __ldcs(&up[2*i]);
    __half2 uh1 = __ldcs(&up[2*i + 1]);
    __half2 xh0 = __ldcs(&xp[2*i]);
    __half2 xh1 = __ldcs(&xp[2*i + 1]);
    float2 u0 = __half22float2(uh0);
    float2 u1 = __half22float2(uh1);
    float2 x0 = __half22float2(xh0);
    float2 x1 = __half22float2(xh1);
    float4 o;
    o.x = fmaf(sc, u0.x, bi + x0.x);
    o.y = fmaf(sc, u0.y, bi + x0.y);
    o.z = fmaf(sc, u1.x, bi + x1.x);
    o.w = fmaf(sc, u1.y, bi + x1.y);
    __stcs(&((float4*)out)[i], o);
}

// ---------------- launch ----------------
extern "C" void kernel_launch(void* const* d_in, const int* in_sizes, int n_in,
                              void* d_out, int out_size) {
    const float* x     = (const float*)d_in[0];
    const float* Wt    = (const float*)d_in[1];
    const float* Wp    = (const float*)d_in[2];
    const float* Wg    = (const float*)d_in[3];
    const float* Wz    = (const float*)d_in[4];
    const float* gamma = (const float*)d_in[5];
    const float* beta  = (const float*)d_in[6];
    float* out = (float*)d_out;

    cudaFuncSetAttribute(k_gemm, cudaFuncAttributeMaxDynamicSharedMemorySize, SMEM_GEMM);

    k_prep<<<NPX + NPA, 256>>>(x, Wt, Wz, Wp, Wg);
    k_gemm<<<dim3(STILES, 8, B_), 256, SMEM_GEMM>>>();
    k_final<<<32768, 256>>>(gamma, beta, out);
}